// round 6
// baseline (speedup 1.0000x reference)
#include <cuda_runtime.h>
#include <math.h>

constexpr int D       = 272;      // capsule feature dim
constexpr int NC      = 19;       // num classes
constexpr int PSTRIDE = 32;       // padded proj row (128B aligned)
constexpr int G_MAX   = 65536;    // B*H*W grid cells
constexpr int MAX_NI  = 8192;
constexpr int ROWS    = 128;      // rows per block (kernel A)
constexpr int CH      = 16;       // d-chunk size (272 = 17 * 16)

__device__ int   g_seg_start[MAX_NI + 1];
__device__ float g_proj[(size_t)G_MAX * PSTRIDE];   // 8.4 MB scratch (L2-resident)

// ---------------------------------------------------------------------------
// Kernel 0: segment boundaries from sorted segment_ids.
// ---------------------------------------------------------------------------
__global__ void seg_bounds_kernel(const int* __restrict__ seg, int P, int NI) {
    int p = blockIdx.x * blockDim.x + threadIdx.x;
    if (p >= P) return;
    int cur  = min(seg[p], NI - 1);
    int prev = (p == 0) ? -1 : min(seg[p - 1], NI - 1);
    for (int s = prev + 1; s <= cur; ++s) g_seg_start[s] = p;
    if (p == P - 1) {
        for (int s = cur + 1; s <= NI; ++s) g_seg_start[s] = P;
    }
}

// ---------------------------------------------------------------------------
// Kernel A: proj = feats @ W   (G x 272) @ (272 x 19) -> (G x 32-padded)
// Block = 128 threads, 128 rows. feats streamed once, coalesced, via smem
// tile (stride 17 = conflict-free). W staged in smem (uniform broadcast reads).
// ---------------------------------------------------------------------------
__global__ __launch_bounds__(ROWS, 4)
void proj_kernel(const float* __restrict__ feats, const float* __restrict__ Wm) {
    __shared__ float sW[D * NC];          // 20.7 KB
    __shared__ float sT[ROWS * 17];       //  8.7 KB, padded stride 17

    const int tid  = threadIdx.x;
    const int base = blockIdx.x * ROWS;

    for (int i = tid; i < D * NC; i += ROWS) sW[i] = Wm[i];

    float acc[NC];
    #pragma unroll
    for (int c = 0; c < NC; ++c) acc[c] = 0.f;

    const float4* f4 = reinterpret_cast<const float4*>(feats);

    for (int ch = 0; ch < D / CH; ++ch) {
        const int d0 = ch * CH;
        __syncthreads();   // prev-chunk reads done (also covers sW on iter 0)
        #pragma unroll
        for (int q = 0; q < 4; ++q) {
            int i   = tid + q * ROWS;          // 0..511 -> 128 rows x 4 float4
            int r   = i >> 2;
            int sub = i & 3;
            float4 v = f4[(size_t)(base + r) * (D / 4) + (d0 >> 2) + sub];
            float* dst = &sT[r * 17 + sub * 4];
            dst[0] = v.x; dst[1] = v.y; dst[2] = v.z; dst[3] = v.w;
        }
        __syncthreads();
        #pragma unroll
        for (int k = 0; k < CH; ++k) {
            float f = sT[tid * 17 + k];              // conflict-free (stride 17)
            const float* w = &sW[(d0 + k) * NC];     // uniform -> broadcast
            #pragma unroll
            for (int c = 0; c < NC; ++c) acc[c] = fmaf(f, w[c], acc[c]);
        }
    }

    // Each thread writes its row's 19 results contiguously (padded to 32).
    float* dst = &g_proj[(size_t)(base + tid) * PSTRIDE];
    #pragma unroll
    for (int c = 0; c < NC; ++c) dst[c] = acc[c];
}

// ---------------------------------------------------------------------------
// Kernel B: one warp per segment. Sum 19-float proj rows (L2-resident),
// divide by count, add bias, sigmoid. Indices staged 32-at-a-time and
// broadcast via shuffle; 4 rows in flight for MLP.
// ---------------------------------------------------------------------------
__global__ __launch_bounds__(256, 8)
void pool_kernel(const int* __restrict__ point_idx,
                 const float* __restrict__ bias,
                 float* __restrict__ out, int NI)
{
    const int warp = blockIdx.x * (blockDim.x >> 5) + (threadIdx.x >> 5);
    if (warp >= NI) return;
    const int lane  = threadIdx.x & 31;
    const int start = g_seg_start[warp];
    const int end   = g_seg_start[warp + 1];

    float acc = 0.f;
    for (int b = start; b < end; b += 32) {
        const int n = min(32, end - b);
        int myidx = (lane < n) ? point_idx[b + lane] : 0;
        int j = 0;
        for (; j + 4 <= n; j += 4) {
            int i0 = __shfl_sync(0xffffffffu, myidx, j);
            int i1 = __shfl_sync(0xffffffffu, myidx, j + 1);
            int i2 = __shfl_sync(0xffffffffu, myidx, j + 2);
            int i3 = __shfl_sync(0xffffffffu, myidx, j + 3);
            if (lane < NC) {
                float v0 = g_proj[(size_t)i0 * PSTRIDE + lane];
                float v1 = g_proj[(size_t)i1 * PSTRIDE + lane];
                float v2 = g_proj[(size_t)i2 * PSTRIDE + lane];
                float v3 = g_proj[(size_t)i3 * PSTRIDE + lane];
                acc += (v0 + v1) + (v2 + v3);
            }
        }
        for (; j < n; ++j) {
            int i0 = __shfl_sync(0xffffffffu, myidx, j);
            if (lane < NC) acc += g_proj[(size_t)i0 * PSTRIDE + lane];
        }
    }

    if (lane < NC) {
        const int cnt = max(end - start, 1);
        float z = acc / (float)cnt + bias[lane];
        out[warp * NC + lane] = 1.0f / (1.0f + expf(-z));
    }
}

// ---------------------------------------------------------------------------
// Launch
// ---------------------------------------------------------------------------
extern "C" void kernel_launch(void* const* d_in, const int* in_sizes, int n_in,
                              void* d_out, int out_size) {
    const float* feats     = (const float*)d_in[0];   // [G, D]
    const float* Wmat      = (const float*)d_in[1];   // [D, NC]
    const float* bias      = (const float*)d_in[2];   // [NC]
    const int*   point_idx = (const int*)  d_in[3];   // [P]
    const int*   seg_ids   = (const int*)  d_in[4];   // [P] sorted
    float*       out       = (float*)d_out;           // [NI, NC]

    const int P = in_sizes[3];
    int G  = in_sizes[0] / D;                         // 65536
    if (G > G_MAX) G = G_MAX;
    int NI = out_size / NC;                           // 4096
    if (NI > MAX_NI) NI = MAX_NI;

    seg_bounds_kernel<<<(P + 255) / 256, 256>>>(seg_ids, P, NI);
    proj_kernel<<<G / ROWS, ROWS>>>(feats, Wmat);
    pool_kernel<<<(NI + 7) / 8, 256>>>(point_idx, bias, out, NI);
}

// round 7
// speedup vs baseline: 1.2186x; 1.2186x over previous
#include <cuda_runtime.h>
#include <math.h>

constexpr int D       = 272;      // capsule feature dim
constexpr int NC      = 19;       // num classes
constexpr int PSTRIDE = 32;       // padded proj row (128B aligned)
constexpr int G_MAX   = 65536;    // B*H*W grid cells
constexpr int MAX_NI  = 8192;
constexpr int BLK     = 128;      // threads per block (kernel A)
constexpr int RPB     = 256;      // rows per block (2 per thread)
constexpr int CHK     = 16;       // k-chunk (272 = 17 * 16)
constexpr int TPAD    = 20;       // sT row stride in floats (bank-conflict-free)

__device__ int   g_seg_start[MAX_NI + 1];
__device__ float g_proj[(size_t)G_MAX * PSTRIDE];   // 8.4 MB scratch (L2-resident)

// ---------------------------------------------------------------------------
// Kernel 0: segment boundaries from sorted segment_ids (4 points per thread).
// ---------------------------------------------------------------------------
__global__ void seg_bounds_kernel(const int* __restrict__ seg, int P, int NI) {
    int q = blockIdx.x * blockDim.x + threadIdx.x;
    int p = q * 4;
    if (p >= P) return;
    int4 s4 = reinterpret_cast<const int4*>(seg)[q];
    int cur[4] = {s4.x, s4.y, s4.z, s4.w};
    int prev = (p == 0) ? -1 : min(seg[p - 1], NI - 1);
    #pragma unroll
    for (int j = 0; j < 4; ++j) {
        if (p + j >= P) break;
        int c = min(cur[j], NI - 1);
        for (int s = prev + 1; s <= c; ++s) g_seg_start[s] = p + j;
        prev = c;
    }
    if (p + 4 >= P) {
        for (int s = prev + 1; s <= NI; ++s) g_seg_start[s] = P;
    }
}

// ---------------------------------------------------------------------------
// Kernel A: proj = feats @ W   (G x 272) @ (272 x 19) -> (G x 32-padded)
// 128 threads x 2 rows each; W transposed in smem so both operands are
// LDS.128. Per 4-k group: 2 f-loads + 19 w-loads (broadcast) + 152 FFMA.
// ---------------------------------------------------------------------------
__global__ __launch_bounds__(BLK, 3)
void proj_kernel(const float* __restrict__ feats, const float* __restrict__ Wm) {
    __shared__ float sWt[NC * D];        // transposed W [c][k], 20.7 KB
    __shared__ float sT[RPB * TPAD];     // 256 rows x 16 k, stride 20 -> 20 KB

    const int tid  = threadIdx.x;
    const int base = blockIdx.x * RPB;

    // Load W coalesced, store transposed: sWt[c*D + k] = Wm[k*NC + c].
    for (int i = tid; i < D * NC; i += BLK) {
        int k = i / NC, c = i % NC;
        sWt[c * D + k] = Wm[i];
    }

    float acc0[NC], acc1[NC];
    #pragma unroll
    for (int c = 0; c < NC; ++c) { acc0[c] = 0.f; acc1[c] = 0.f; }

    const float4* f4  = reinterpret_cast<const float4*>(feats);
    const float4* sW4 = reinterpret_cast<const float4*>(sWt);
    const int r0 = tid, r1 = tid + BLK;

    for (int ch = 0; ch < D / CHK; ++ch) {
        const int d4 = ch * (CHK / 4);     // float4 offset within a row
        __syncthreads();                    // prev-chunk reads done (covers sWt iter 0)
        // Stage 256 rows x 16 floats: 4 consecutive lanes fetch 64B of one row.
        #pragma unroll
        for (int qq = 0; qq < 8; ++qq) {
            int i   = tid + qq * BLK;       // 0..1023
            int r   = i >> 2;
            int sub = i & 3;
            float4 v = f4[(size_t)(base + r) * (D / 4) + d4 + sub];
            float* dst = &sT[r * TPAD + sub * 4];
            reinterpret_cast<float4*>(dst)[0] = v;
        }
        __syncthreads();
        const float4* sT4 = reinterpret_cast<const float4*>(sT);
        #pragma unroll
        for (int k4 = 0; k4 < CHK / 4; ++k4) {
            float4 a = sT4[r0 * (TPAD / 4) + k4];   // stride-5 float4: conflict-free
            float4 b = sT4[r1 * (TPAD / 4) + k4];
            #pragma unroll
            for (int c = 0; c < NC; ++c) {
                float4 w = sW4[c * (D / 4) + d4 + k4];   // warp-uniform broadcast
                acc0[c] = fmaf(a.x, w.x, acc0[c]);
                acc0[c] = fmaf(a.y, w.y, acc0[c]);
                acc0[c] = fmaf(a.z, w.z, acc0[c]);
                acc0[c] = fmaf(a.w, w.w, acc0[c]);
                acc1[c] = fmaf(b.x, w.x, acc1[c]);
                acc1[c] = fmaf(b.y, w.y, acc1[c]);
                acc1[c] = fmaf(b.z, w.z, acc1[c]);
                acc1[c] = fmaf(b.w, w.w, acc1[c]);
            }
        }
    }

    // Write both rows, vectorized (rows are 128B-aligned in g_proj).
    float* d0 = &g_proj[(size_t)(base + r0) * PSTRIDE];
    float* d1 = &g_proj[(size_t)(base + r1) * PSTRIDE];
    #pragma unroll
    for (int c4 = 0; c4 < 4; ++c4) {
        reinterpret_cast<float4*>(d0)[c4] =
            make_float4(acc0[c4*4], acc0[c4*4+1], acc0[c4*4+2], acc0[c4*4+3]);
        reinterpret_cast<float4*>(d1)[c4] =
            make_float4(acc1[c4*4], acc1[c4*4+1], acc1[c4*4+2], acc1[c4*4+3]);
    }
    d0[16] = acc0[16]; d0[17] = acc0[17]; d0[18] = acc0[18];
    d1[16] = acc1[16]; d1[17] = acc1[17]; d1[18] = acc1[18];
}

// ---------------------------------------------------------------------------
// Kernel B: one warp per segment. Sum 19-float proj rows (L2-resident),
// divide by count, add bias, sigmoid. Indices broadcast via shuffle, MLP=4.
// ---------------------------------------------------------------------------
__global__ __launch_bounds__(256, 8)
void pool_kernel(const int* __restrict__ point_idx,
                 const float* __restrict__ bias,
                 float* __restrict__ out, int NI)
{
    const int warp = blockIdx.x * (blockDim.x >> 5) + (threadIdx.x >> 5);
    if (warp >= NI) return;
    const int lane  = threadIdx.x & 31;
    const int start = g_seg_start[warp];
    const int end   = g_seg_start[warp + 1];

    float acc = 0.f;
    for (int b = start; b < end; b += 32) {
        const int n = min(32, end - b);
        int myidx = (lane < n) ? point_idx[b + lane] : 0;
        int j = 0;
        for (; j + 4 <= n; j += 4) {
            int i0 = __shfl_sync(0xffffffffu, myidx, j);
            int i1 = __shfl_sync(0xffffffffu, myidx, j + 1);
            int i2 = __shfl_sync(0xffffffffu, myidx, j + 2);
            int i3 = __shfl_sync(0xffffffffu, myidx, j + 3);
            if (lane < NC) {
                float v0 = g_proj[(size_t)i0 * PSTRIDE + lane];
                float v1 = g_proj[(size_t)i1 * PSTRIDE + lane];
                float v2 = g_proj[(size_t)i2 * PSTRIDE + lane];
                float v3 = g_proj[(size_t)i3 * PSTRIDE + lane];
                acc += (v0 + v1) + (v2 + v3);
            }
        }
        for (; j < n; ++j) {
            int i0 = __shfl_sync(0xffffffffu, myidx, j);
            if (lane < NC) acc += g_proj[(size_t)i0 * PSTRIDE + lane];
        }
    }

    if (lane < NC) {
        const int cnt = max(end - start, 1);
        float z = acc / (float)cnt + bias[lane];
        out[warp * NC + lane] = 1.0f / (1.0f + expf(-z));
    }
}

// ---------------------------------------------------------------------------
// Launch
// ---------------------------------------------------------------------------
extern "C" void kernel_launch(void* const* d_in, const int* in_sizes, int n_in,
                              void* d_out, int out_size) {
    const float* feats     = (const float*)d_in[0];   // [G, D]
    const float* Wmat      = (const float*)d_in[1];   // [D, NC]
    const float* bias      = (const float*)d_in[2];   // [NC]
    const int*   point_idx = (const int*)  d_in[3];   // [P]
    const int*   seg_ids   = (const int*)  d_in[4];   // [P] sorted
    float*       out       = (float*)d_out;           // [NI, NC]

    const int P = in_sizes[3];
    int G  = in_sizes[0] / D;                         // 65536
    if (G > G_MAX) G = G_MAX;
    int NI = out_size / NC;                           // 4096
    if (NI > MAX_NI) NI = MAX_NI;

    const int Q = (P + 3) / 4;
    seg_bounds_kernel<<<(Q + 255) / 256, 256>>>(seg_ids, P, NI);
    proj_kernel<<<G / RPB, BLK>>>(feats, Wmat);
    pool_kernel<<<(NI + 7) / 8, 256>>>(point_idx, bias, out, NI);
}